// round 8
// baseline (speedup 1.0000x reference)
#include <cuda_runtime.h>
#include <cuda_bf16.h>
#include <math.h>
#include <limits.h>

// ---------------- problem constants ----------------
#define KSEL   50
#define FDIM   90
#define PCAP   4096
#define RMAX   256
#define NMAX   600000
#define SMAX   16
#define NB     240

// ---------------- device scratch ----------------
__device__ int    g_counts[RMAX];
__device__ int    g_offsets[RMAX];
__device__ int    g_bc[NB * RMAX];
__device__ int    g_bbase[NB * RMAX];
__device__ float4 g_packed[NMAX];
__device__ float  g_feat[RMAX * KSEL * FDIM];
__device__ float  g_part[SMAX * RMAX * 512];
__device__ float  g_hA[RMAX * 512];
__device__ float  g_hB[RMAX * 512];

// ---------------- grouping ----------------
__global__ void blockhist_kernel(const int* __restrict__ idx, int Np, int chunk) {
    __shared__ int sh[RMAX];
    int b = blockIdx.x;
    int t = threadIdx.x;
    if (t < RMAX) sh[t] = 0;
    __syncthreads();
    int i0 = b * chunk;
    int i1 = i0 + chunk; if (i1 > Np) i1 = Np;
    for (int i = i0 + t; i < i1; i += blockDim.x)
        atomicAdd(&sh[idx[i]], 1);
    __syncthreads();
    if (t < RMAX) g_bc[b * RMAX + t] = sh[t];
}

__global__ void totals_scan_kernel() {
    __shared__ int wsum[8];
    int r = threadIdx.x;
    int c = 0;
    for (int b = 0; b < NB; b++) c += g_bc[b * RMAX + r];
    g_counts[r] = c;
    int v = c;
    for (int o = 1; o < 32; o <<= 1) {
        int x = __shfl_up_sync(~0u, v, o);
        if ((r & 31) >= o) v += x;
    }
    if ((r & 31) == 31) wsum[r >> 5] = v;
    __syncthreads();
    if (r < 8) {
        int s = wsum[r];
        for (int o = 1; o < 8; o <<= 1) {
            int x = __shfl_up_sync(0xff, s, o);
            if (r >= o) s += x;
        }
        wsum[r] = s;
    }
    __syncthreads();
    int pre = (r >= 32) ? wsum[(r >> 5) - 1] : 0;
    g_offsets[r] = pre + v - c;
}

__global__ void blockbase_kernel() {
    __shared__ int wsum[8];
    int r = blockIdx.x;
    int t = threadIdx.x;
    int c = (t < NB) ? g_bc[t * RMAX + r] : 0;
    int v = c;
    for (int o = 1; o < 32; o <<= 1) {
        int x = __shfl_up_sync(~0u, v, o);
        if ((t & 31) >= o) v += x;
    }
    if ((t & 31) == 31) wsum[t >> 5] = v;
    __syncthreads();
    if (t < 8) {
        int s = wsum[t];
        for (int o = 1; o < 8; o <<= 1) {
            int x = __shfl_up_sync(0xff, s, o);
            if (t >= o) s += x;
        }
        wsum[t] = s;
    }
    __syncthreads();
    int pre = (t >= 32) ? wsum[(t >> 5) - 1] : 0;
    if (t < NB) g_bbase[t * RMAX + r] = g_offsets[r] + pre + v - c;
}

__global__ void scatter_kernel(const int* __restrict__ idx,
                               const float* __restrict__ coords,
                               int Np, int chunk) {
    __shared__ int sc[RMAX];
    int b = blockIdx.x;
    int t = threadIdx.x;
    if (t < RMAX) sc[t] = g_bbase[b * RMAX + t];
    __syncthreads();
    int i0 = b * chunk;
    int i1 = i0 + chunk; if (i1 > Np) i1 = Np;
    for (int i = i0 + t; i < i1; i += blockDim.x) {
        int r = idx[i];
        int slot = atomicAdd(&sc[r], 1);
        float4 p;
        p.x = coords[3 * i + 0];
        p.y = coords[3 * i + 1];
        p.z = coords[3 * i + 2];
        p.w = __int_as_float(i);
        g_packed[slot] = p;
    }
}

// ---------------- FPS (+fused gather): R3 two-barrier structure ----------------
#define FPW 8
__global__ __launch_bounds__(512, 2) void fps_kernel(const float* __restrict__ feats) {
    extern __shared__ float sm[];
    float* sx = sm;
    float* sy = sx + PCAP;
    float* sz = sy + PCAP;

    __shared__ float rv[16];
    __shared__ int   rid[16], rpos[16];
    __shared__ float lastx, lasty, lastz;
    __shared__ int   ssel[KSEL];

    int r = blockIdx.x;
    int P = g_counts[r];
    if (P > PCAP) P = PCAP;
    int tid = threadIdx.x;
    const size_t rowbase = (size_t)r * (KSEL * FDIM);

    if (P == 0) {
        for (int e = tid; e < KSEL * FDIM; e += 512)
            g_feat[rowbase + e] = 0.0f;
        return;
    }
    int off = g_offsets[r];

    float rx[FPW], ry[FPW], rz[FPW], rd[FPW];
    int   rgid[FPW];

#pragma unroll
    for (int jj = 0; jj < FPW; jj++) {
        int j = tid + jj * 512;
        if (j < P) {
            float4 p = g_packed[off + j];
            rx[jj] = p.x; ry[jj] = p.y; rz[jj] = p.z;
            rgid[jj] = __float_as_int(p.w);
            sx[j] = p.x; sy[j] = p.y; sz[j] = p.z;
        }
        rd[jj] = 1e10f;
    }
    __syncthreads();

    // first selection: minimum global id
    {
        int bi = INT_MAX, bp = 0;
#pragma unroll
        for (int jj = 0; jj < FPW; jj++) {
            int j = tid + jj * 512;
            if (j < P && rgid[jj] < bi) { bi = rgid[jj]; bp = j; }
        }
        for (int o = 16; o > 0; o >>= 1) {
            int oi = __shfl_down_sync(~0u, bi, o);
            int op = __shfl_down_sync(~0u, bp, o);
            if (oi < bi) { bi = oi; bp = op; }
        }
        if ((tid & 31) == 0) { rid[tid >> 5] = bi; rpos[tid >> 5] = bp; }
        __syncthreads();
        if (tid < 32) {
            int v  = (tid < 16) ? rid[tid]  : INT_MAX;
            int pp = (tid < 16) ? rpos[tid] : 0;
            for (int o = 8; o > 0; o >>= 1) {
                int oi = __shfl_down_sync(~0u, v, o);
                int op = __shfl_down_sync(~0u, pp, o);
                if (oi < v) { v = oi; pp = op; }
            }
            if (tid == 0) {
                ssel[0] = v;
                lastx = sx[pp]; lasty = sy[pp]; lastz = sz[pp];
            }
        }
        __syncthreads();
    }

    for (int it = 1; it < KSEL; it++) {
        float lx = lastx, ly = lasty, lz = lastz;
        float bv = -2.0f; int bi = INT_MAX; int bp = 0;
#pragma unroll
        for (int jj = 0; jj < FPW; jj++) {
            int j = tid + jj * 512;
            if (j < P) {
                float dx = rx[jj] - lx, dy = ry[jj] - ly, dz = rz[jj] - lz;
                float d  = dx * dx + dy * dy + dz * dz;
                float nd = fminf(rd[jj], d);
                rd[jj] = nd;
                if (nd > bv || (nd == bv && rgid[jj] < bi)) { bv = nd; bi = rgid[jj]; bp = j; }
            }
        }
        for (int o = 16; o > 0; o >>= 1) {
            float ov = __shfl_down_sync(~0u, bv, o);
            int   oi = __shfl_down_sync(~0u, bi, o);
            int   op = __shfl_down_sync(~0u, bp, o);
            if (ov > bv || (ov == bv && oi < bi)) { bv = ov; bi = oi; bp = op; }
        }
        if ((tid & 31) == 0) { rv[tid >> 5] = bv; rid[tid >> 5] = bi; rpos[tid >> 5] = bp; }
        __syncthreads();
        if (tid < 32) {
            float v  = (tid < 16) ? rv[tid]   : -3.0f;
            int   id = (tid < 16) ? rid[tid]  : INT_MAX;
            int   pp = (tid < 16) ? rpos[tid] : 0;
            for (int o = 8; o > 0; o >>= 1) {
                float ov = __shfl_down_sync(~0u, v, o);
                int   oi = __shfl_down_sync(~0u, id, o);
                int   op = __shfl_down_sync(~0u, pp, o);
                if (ov > v || (ov == v && oi < id)) { v = ov; id = oi; pp = op; }
            }
            if (tid == 0) {
                ssel[it] = id;
                lastx = sx[pp]; lasty = sy[pp]; lastz = sz[pp];
            }
        }
        __syncthreads();
    }

    for (int e = tid; e < KSEL * FDIM; e += 512) {
        int k = e / FDIM;
        int f = e - k * FDIM;
        g_feat[rowbase + e] = feats[(size_t)ssel[k] * FDIM + f];
    }
}

// ---------------- 3xTF32 helpers ----------------
__device__ __forceinline__ void split_tf32(float x, unsigned& hi, unsigned& lo) {
    unsigned h;
    asm("cvt.rna.tf32.f32 %0, %1;" : "=r"(h) : "f"(x));
    float rres = x - __uint_as_float(h);
    unsigned l;
    asm("cvt.rna.tf32.f32 %0, %1;" : "=r"(l) : "f"(rres));
    hi = h; lo = l;
}

#define MMA_TF32(D, A0, A1, A2, A3, B0, B1)                                   \
    asm volatile("mma.sync.aligned.m16n8k8.row.col.f32.tf32.tf32.f32 "        \
                 "{%0,%1,%2,%3},{%4,%5,%6,%7},{%8,%9},{%0,%1,%2,%3};"         \
                 : "+f"(D[0]), "+f"(D[1]), "+f"(D[2]), "+f"(D[3])             \
                 : "r"(A0), "r"(A1), "r"(A2), "r"(A3), "r"(B0), "r"(B1))

// ---------------- split-K GEMM for layer 1 (K=4500) ----------------
__global__ __launch_bounds__(128) void gemm_tc_kernel(const float* __restrict__ A,
                                                      const float* __restrict__ B,
                                                      int M, int N, int K, int chunk) {
    __shared__ float As[64][36];
    __shared__ float Bs[32][72];
    int s  = blockIdx.z;
    int k0 = s * chunk;
    int k1 = k0 + chunk; if (k1 > K) k1 = K;
    int m0 = blockIdx.y * 64, n0 = blockIdx.x * 64;
    int tid = threadIdx.x;
    int lane = tid & 31, w = tid >> 5;
    int wm = w >> 1, wn = w & 1;
    int g = lane >> 2, q = lane & 3;

    float d[2][4][4];
#pragma unroll
    for (int mi = 0; mi < 2; mi++)
#pragma unroll
        for (int ni = 0; ni < 4; ni++)
#pragma unroll
            for (int e = 0; e < 4; e++) d[mi][ni][e] = 0.0f;

    for (int kb = k0; kb < k1; kb += 32) {
        if (kb + 32 <= k1) {
#pragma unroll
            for (int i = 0; i < 4; i++) {
                int id = tid + i * 128;
                int row = id >> 3, c4 = id & 7;
                float4 v = *(const float4*)&A[(size_t)(m0 + row) * K + kb + c4 * 4];
                *(float4*)&As[row][c4 * 4] = v;
            }
#pragma unroll
            for (int i = 0; i < 4; i++) {
                int id = tid + i * 128;
                int row = id >> 4, c4 = id & 15;
                float4 v = *(const float4*)&B[(size_t)(kb + row) * N + n0 + c4 * 4];
                *(float4*)&Bs[row][c4 * 4] = v;
            }
        } else {
            for (int i = tid; i < 64 * 32; i += 128) {
                int row = i >> 5, c = i & 31;
                int kg = kb + c;
                As[row][c] = (kg < k1) ? A[(size_t)(m0 + row) * K + kg] : 0.0f;
            }
            for (int i = tid; i < 32 * 64; i += 128) {
                int row = i >> 6, c = i & 63;
                int kg = kb + row;
                Bs[row][c] = (kg < k1) ? B[(size_t)kg * N + n0 + c] : 0.0f;
            }
        }
        __syncthreads();
#pragma unroll
        for (int k8 = 0; k8 < 32; k8 += 8) {
            unsigned ah[2][4], al[2][4], bh[4][2], bl[4][2];
#pragma unroll
            for (int mi = 0; mi < 2; mi++) {
                int r0 = wm * 32 + mi * 16 + g;
                split_tf32(As[r0][k8 + q],         ah[mi][0], al[mi][0]);
                split_tf32(As[r0 + 8][k8 + q],     ah[mi][1], al[mi][1]);
                split_tf32(As[r0][k8 + q + 4],     ah[mi][2], al[mi][2]);
                split_tf32(As[r0 + 8][k8 + q + 4], ah[mi][3], al[mi][3]);
            }
#pragma unroll
            for (int ni = 0; ni < 4; ni++) {
                int col = wn * 32 + ni * 8 + g;
                split_tf32(Bs[k8 + q][col],     bh[ni][0], bl[ni][0]);
                split_tf32(Bs[k8 + q + 4][col], bh[ni][1], bl[ni][1]);
            }
#pragma unroll
            for (int mi = 0; mi < 2; mi++)
#pragma unroll
                for (int ni = 0; ni < 4; ni++) {
                    MMA_TF32(d[mi][ni], ah[mi][0], ah[mi][1], ah[mi][2], ah[mi][3],
                             bh[ni][0], bh[ni][1]);
                    MMA_TF32(d[mi][ni], ah[mi][0], ah[mi][1], ah[mi][2], ah[mi][3],
                             bl[ni][0], bl[ni][1]);
                    MMA_TF32(d[mi][ni], al[mi][0], al[mi][1], al[mi][2], al[mi][3],
                             bh[ni][0], bh[ni][1]);
                }
        }
        __syncthreads();
    }

    float* P = g_part + (size_t)s * M * N;
#pragma unroll
    for (int mi = 0; mi < 2; mi++) {
#pragma unroll
        for (int ni = 0; ni < 4; ni++) {
            int m_ = m0 + wm * 32 + mi * 16 + g;
            int n_ = n0 + wn * 32 + ni * 8 + q * 2;
            *(float2*)&P[(size_t)m_ * N + n_]       = make_float2(d[mi][ni][0], d[mi][ni][1]);
            *(float2*)&P[(size_t)(m_ + 8) * N + n_] = make_float2(d[mi][ni][2], d[mi][ni][3]);
        }
    }
}

// ---------------- bn_combine for layer 1 ----------------
__global__ __launch_bounds__(256) void bn_combine_kernel(const float* __restrict__ bias,
                                                         const float* __restrict__ gam,
                                                         const float* __restrict__ bet,
                                                         float* __restrict__ out,
                                                         int M, int N, int S, int relu) {
    __shared__ float red[256];
    __shared__ float cmean[8], cvar[8];
    int t = threadIdx.x;
    int n0 = blockIdx.x * 8;
    int col = n0 + (t & 7);
    int mrow = t >> 3;

    float bn = bias[col];
    float v[8];
    float psum = 0.0f;
#pragma unroll
    for (int j = 0; j < 8; j++) {
        int m = mrow + 32 * j;
        float acc = bn;
        for (int s = 0; s < S; s++)
            acc += g_part[(size_t)s * M * N + (size_t)m * N + col];
        v[j] = acc;
        psum += acc;
    }
    red[t] = psum;
    __syncthreads();
    for (int st = 128; st >= 8; st >>= 1) {
        if (t < st) red[t] += red[t + st];
        __syncthreads();
    }
    if (t < 8) cmean[t] = red[t] / (float)M;
    __syncthreads();
    float mean = cmean[t & 7];

    float pss = 0.0f;
#pragma unroll
    for (int j = 0; j < 8; j++) {
        float dd = v[j] - mean;
        pss += dd * dd;
    }
    red[t] = pss;
    __syncthreads();
    for (int st = 128; st >= 8; st >>= 1) {
        if (t < st) red[t] += red[t + st];
        __syncthreads();
    }
    if (t < 8) cvar[t] = red[t] / (float)M;
    __syncthreads();
    float inv = rsqrtf(cvar[t & 7] + 1e-5f);
    float gm = gam[col], bt = bet[col];

#pragma unroll
    for (int j = 0; j < 8; j++) {
        int m = mrow + 32 * j;
        float y = gm * (v[j] - mean) * inv + bt;
        if (relu) y = fmaxf(y, 0.0f);
        out[(size_t)m * N + col] = y;
    }
}

// ---------------- fused GEMM + BN for tail layers (M=256, block = 256x64 strip) -
// grid = N/64 blocks, 512 threads. Dynamic smem layout:
//   phase 1: A[256][36] at 0 (9216 floats), B[32][72] at 9216 (2304 floats)
//   phase 2: OUT[256][68] at 0 (17408 floats)
__global__ __launch_bounds__(512, 1) void fused_layer_kernel(
    const float* __restrict__ A, const float* __restrict__ B,
    const float* __restrict__ bias, const float* __restrict__ gam,
    const float* __restrict__ bet, float* __restrict__ out,
    int K, int N, int relu) {
    extern __shared__ float fsm[];
    __shared__ float red[512];
    __shared__ float cmean[64], cvar[64];

    int n0 = blockIdx.x * 64;
    int tid = threadIdx.x;
    int lane = tid & 31, w = tid >> 5;
    int mq = w & 3;        // 64-row quadrant
    int nq = w >> 2;       // 16-col group
    int g = lane >> 2, q = lane & 3;

    float d[4][2][4];
#pragma unroll
    for (int mi = 0; mi < 4; mi++)
#pragma unroll
        for (int ni = 0; ni < 2; ni++)
#pragma unroll
            for (int e = 0; e < 4; e++) d[mi][ni][e] = 0.0f;

    for (int kb = 0; kb < K; kb += 32) {
#pragma unroll
        for (int i = 0; i < 4; i++) {
            int id = tid + i * 512;
            int row = id >> 3, c4 = id & 7;
            float4 v = *(const float4*)&A[(size_t)row * K + kb + c4 * 4];
            *(float4*)&fsm[row * 36 + c4 * 4] = v;
        }
        {
            int row = tid >> 4, c4 = tid & 15;
            float4 v = *(const float4*)&B[(size_t)(kb + row) * N + n0 + c4 * 4];
            *(float4*)&fsm[9216 + row * 72 + c4 * 4] = v;
        }
        __syncthreads();
#pragma unroll
        for (int k8 = 0; k8 < 32; k8 += 8) {
            unsigned ah[4][4], al[4][4], bh[2][2], bl[2][2];
#pragma unroll
            for (int mi = 0; mi < 4; mi++) {
                int r0 = mq * 64 + mi * 16 + g;
                split_tf32(fsm[r0 * 36 + k8 + q],           ah[mi][0], al[mi][0]);
                split_tf32(fsm[(r0 + 8) * 36 + k8 + q],     ah[mi][1], al[mi][1]);
                split_tf32(fsm[r0 * 36 + k8 + q + 4],       ah[mi][2], al[mi][2]);
                split_tf32(fsm[(r0 + 8) * 36 + k8 + q + 4], ah[mi][3], al[mi][3]);
            }
#pragma unroll
            for (int ni = 0; ni < 2; ni++) {
                int col = nq * 16 + ni * 8 + g;
                split_tf32(fsm[9216 + (k8 + q) * 72 + col],     bh[ni][0], bl[ni][0]);
                split_tf32(fsm[9216 + (k8 + q + 4) * 72 + col], bh[ni][1], bl[ni][1]);
            }
#pragma unroll
            for (int mi = 0; mi < 4; mi++)
#pragma unroll
                for (int ni = 0; ni < 2; ni++) {
                    MMA_TF32(d[mi][ni], ah[mi][0], ah[mi][1], ah[mi][2], ah[mi][3],
                             bh[ni][0], bh[ni][1]);
                    MMA_TF32(d[mi][ni], ah[mi][0], ah[mi][1], ah[mi][2], ah[mi][3],
                             bl[ni][0], bl[ni][1]);
                    MMA_TF32(d[mi][ni], al[mi][0], al[mi][1], al[mi][2], al[mi][3],
                             bh[ni][0], bh[ni][1]);
                }
        }
        __syncthreads();
    }

    // write accum + bias into OUT smem tile [256][68]
#pragma unroll
    for (int mi = 0; mi < 4; mi++) {
#pragma unroll
        for (int ni = 0; ni < 2; ni++) {
            int m_ = mq * 64 + mi * 16 + g;
            int n_ = nq * 16 + ni * 8 + q * 2;
            float b0 = bias[n0 + n_], b1 = bias[n0 + n_ + 1];
            fsm[m_ * 68 + n_]           = d[mi][ni][0] + b0;
            fsm[m_ * 68 + n_ + 1]       = d[mi][ni][1] + b1;
            fsm[(m_ + 8) * 68 + n_]     = d[mi][ni][2] + b0;
            fsm[(m_ + 8) * 68 + n_ + 1] = d[mi][ni][3] + b1;
        }
    }
    __syncthreads();

    // BN stats: 8 threads per column, 32 rows each
    int col = tid & 63;
    int mr  = tid >> 6;
    float psum = 0.0f;
#pragma unroll
    for (int j = 0; j < 32; j++)
        psum += fsm[(mr * 32 + j) * 68 + col];
    red[tid] = psum;
    __syncthreads();
    for (int st = 256; st >= 64; st >>= 1) {
        if (tid < st) red[tid] += red[tid + st];
        __syncthreads();
    }
    if (tid < 64) cmean[tid] = red[tid] * (1.0f / 256.0f);
    __syncthreads();
    float mean = cmean[col];

    float pss = 0.0f;
#pragma unroll
    for (int j = 0; j < 32; j++) {
        float dd = fsm[(mr * 32 + j) * 68 + col] - mean;
        pss += dd * dd;
    }
    red[tid] = pss;
    __syncthreads();
    for (int st = 256; st >= 64; st >>= 1) {
        if (tid < st) red[tid] += red[tid + st];
        __syncthreads();
    }
    if (tid < 64) cvar[tid] = red[tid] * (1.0f / 256.0f);
    __syncthreads();
    float inv = rsqrtf(cvar[col] + 1e-5f);
    float gm = gam[n0 + col], bt = bet[n0 + col];

#pragma unroll
    for (int j = 0; j < 32; j++) {
        int m = mr * 32 + j;
        float y = gm * (fsm[m * 68 + col] - mean) * inv + bt;
        if (relu) y = fmaxf(y, 0.0f);
        out[(size_t)m * N + n0 + col] = y;
    }
}

// ---------------- host ----------------
extern "C" void kernel_launch(void* const* d_in, const int* in_sizes, int n_in,
                              void* d_out, int out_size) {
    const int*   roi_idx = (const int*)d_in[1];
    const float* feats   = (const float*)d_in[2];
    const float* coords  = (const float*)d_in[3];
    const float* w1 = (const float*)d_in[4],  *b1 = (const float*)d_in[5];
    const float* g1 = (const float*)d_in[6],  *be1 = (const float*)d_in[7];
    const float* w2 = (const float*)d_in[8],  *b2 = (const float*)d_in[9];
    const float* g2 = (const float*)d_in[10], *be2 = (const float*)d_in[11];
    const float* w3 = (const float*)d_in[12], *b3 = (const float*)d_in[13];
    const float* g3 = (const float*)d_in[14], *be3 = (const float*)d_in[15];
    const float* w4 = (const float*)d_in[16], *b4 = (const float*)d_in[17];
    const float* g4 = (const float*)d_in[18], *be4 = (const float*)d_in[19];
    const float* w5 = (const float*)d_in[20], *b5 = (const float*)d_in[21];
    const float* g5 = (const float*)d_in[22], *be5 = (const float*)d_in[23];

    int R  = out_size / 512;
    int Np = in_sizes[1];
    float* out = (float*)d_out;

    float *feat_p, *hA_p, *hB_p;
    cudaGetSymbolAddress((void**)&feat_p, g_feat);
    cudaGetSymbolAddress((void**)&hA_p,  g_hA);
    cudaGetSymbolAddress((void**)&hB_p,  g_hB);

    const int FPS_SMEM = PCAP * 3 * (int)sizeof(float);           // 48KB
    const int FUSED_SMEM = 256 * 68 * (int)sizeof(float);         // 69632B
    cudaFuncSetAttribute(fps_kernel, cudaFuncAttributeMaxDynamicSharedMemorySize, FPS_SMEM);
    cudaFuncSetAttribute(fused_layer_kernel, cudaFuncAttributeMaxDynamicSharedMemorySize, FUSED_SMEM);

    // grouping
    int chunk = (Np + NB - 1) / NB;
    blockhist_kernel<<<NB, 512>>>(roi_idx, Np, chunk);
    totals_scan_kernel<<<1, 256>>>();
    blockbase_kernel<<<RMAX, 256>>>();
    scatter_kernel<<<NB, 512>>>(roi_idx, coords, Np, chunk);

    // FPS + fused gather
    fps_kernel<<<R, 512, FPS_SMEM>>>(feats);

    // layer 1: split-K GEMM (K=4500) + bn_combine
    {
        int K = KSEL * FDIM, N = 256, S = 8;
        int ck = ((K + S - 1) / S + 31) & ~31;
        dim3 grid(N / 64, R / 64, S);
        gemm_tc_kernel<<<grid, 128>>>(feat_p, w1, R, N, K, ck);
        bn_combine_kernel<<<N / 8, 256>>>(b1, g1, be1, hA_p, R, N, S, 1);
    }
    // layers 2-5: fused GEMM+BN (full-column-strip blocks)
    fused_layer_kernel<<<256 / 64, 512, FUSED_SMEM>>>(hA_p, w2, b2, g2, be2, hB_p, 256, 256, 1);
    fused_layer_kernel<<<512 / 64, 512, FUSED_SMEM>>>(hB_p, w3, b3, g3, be3, hA_p, 256, 512, 0);
    fused_layer_kernel<<<256 / 64, 512, FUSED_SMEM>>>(hA_p, w4, b4, g4, be4, hB_p, 512, 256, 1);
    fused_layer_kernel<<<512 / 64, 512, FUSED_SMEM>>>(hB_p, w5, b5, g5, be5, out,  256, 512, 1);
}

// round 9
// speedup vs baseline: 1.6154x; 1.6154x over previous
#include <cuda_runtime.h>
#include <cuda_bf16.h>
#include <math.h>
#include <limits.h>

// ---------------- problem constants ----------------
#define KSEL   50
#define FDIM   90
#define PCAP   4096
#define RMAX   256
#define NMAX   600000
#define SMAX   16
#define NB     240

// ---------------- device scratch ----------------
__device__ int    g_counts[RMAX];
__device__ int    g_offsets[RMAX];
__device__ int    g_bc[NB * RMAX];
__device__ int    g_bbase[NB * RMAX];
__device__ float4 g_packed[NMAX];
__device__ float  g_feat[RMAX * KSEL * FDIM];
__device__ float  g_part[SMAX * RMAX * 512];
__device__ float  g_hA[RMAX * 512];
__device__ float  g_hB[RMAX * 512];

// ---------------- grouping ----------------
__global__ void blockhist_kernel(const int* __restrict__ idx, int Np, int chunk) {
    __shared__ int sh[RMAX];
    int b = blockIdx.x;
    int t = threadIdx.x;
    if (t < RMAX) sh[t] = 0;
    __syncthreads();
    int i0 = b * chunk;
    int i1 = i0 + chunk; if (i1 > Np) i1 = Np;
    for (int i = i0 + t; i < i1; i += blockDim.x)
        atomicAdd(&sh[idx[i]], 1);
    __syncthreads();
    if (t < RMAX) g_bc[b * RMAX + t] = sh[t];
}

__global__ void totals_scan_kernel() {
    __shared__ int wsum[8];
    int r = threadIdx.x;
    int c = 0;
    for (int b = 0; b < NB; b++) c += g_bc[b * RMAX + r];
    g_counts[r] = c;
    int v = c;
    for (int o = 1; o < 32; o <<= 1) {
        int x = __shfl_up_sync(~0u, v, o);
        if ((r & 31) >= o) v += x;
    }
    if ((r & 31) == 31) wsum[r >> 5] = v;
    __syncthreads();
    if (r < 8) {
        int s = wsum[r];
        for (int o = 1; o < 8; o <<= 1) {
            int x = __shfl_up_sync(0xff, s, o);
            if (r >= o) s += x;
        }
        wsum[r] = s;
    }
    __syncthreads();
    int pre = (r >= 32) ? wsum[(r >> 5) - 1] : 0;
    g_offsets[r] = pre + v - c;
}

__global__ void blockbase_kernel() {
    __shared__ int wsum[8];
    int r = blockIdx.x;
    int t = threadIdx.x;
    int c = (t < NB) ? g_bc[t * RMAX + r] : 0;
    int v = c;
    for (int o = 1; o < 32; o <<= 1) {
        int x = __shfl_up_sync(~0u, v, o);
        if ((t & 31) >= o) v += x;
    }
    if ((t & 31) == 31) wsum[t >> 5] = v;
    __syncthreads();
    if (t < 8) {
        int s = wsum[t];
        for (int o = 1; o < 8; o <<= 1) {
            int x = __shfl_up_sync(0xff, s, o);
            if (t >= o) s += x;
        }
        wsum[t] = s;
    }
    __syncthreads();
    int pre = (t >= 32) ? wsum[(t >> 5) - 1] : 0;
    if (t < NB) g_bbase[t * RMAX + r] = g_offsets[r] + pre + v - c;
}

__global__ void scatter_kernel(const int* __restrict__ idx,
                               const float* __restrict__ coords,
                               int Np, int chunk) {
    __shared__ int sc[RMAX];
    int b = blockIdx.x;
    int t = threadIdx.x;
    if (t < RMAX) sc[t] = g_bbase[b * RMAX + t];
    __syncthreads();
    int i0 = b * chunk;
    int i1 = i0 + chunk; if (i1 > Np) i1 = Np;
    for (int i = i0 + t; i < i1; i += blockDim.x) {
        int r = idx[i];
        int slot = atomicAdd(&sc[r], 1);
        float4 p;
        p.x = coords[3 * i + 0];
        p.y = coords[3 * i + 1];
        p.z = coords[3 * i + 2];
        p.w = __int_as_float(i);
        g_packed[slot] = p;
    }
}

// ---------------- FPS (+fused gather): R3 two-barrier structure ----------------
#define FPW 8
__global__ __launch_bounds__(512, 2) void fps_kernel(const float* __restrict__ feats) {
    extern __shared__ float sm[];
    float* sx = sm;
    float* sy = sx + PCAP;
    float* sz = sy + PCAP;

    __shared__ float rv[16];
    __shared__ int   rid[16], rpos[16];
    __shared__ float lastx, lasty, lastz;
    __shared__ int   ssel[KSEL];

    int r = blockIdx.x;
    int P = g_counts[r];
    if (P > PCAP) P = PCAP;
    int tid = threadIdx.x;
    const size_t rowbase = (size_t)r * (KSEL * FDIM);

    if (P == 0) {
        for (int e = tid; e < KSEL * FDIM; e += 512)
            g_feat[rowbase + e] = 0.0f;
        return;
    }
    int off = g_offsets[r];

    float rx[FPW], ry[FPW], rz[FPW], rd[FPW];
    int   rgid[FPW];

#pragma unroll
    for (int jj = 0; jj < FPW; jj++) {
        int j = tid + jj * 512;
        if (j < P) {
            float4 p = g_packed[off + j];
            rx[jj] = p.x; ry[jj] = p.y; rz[jj] = p.z;
            rgid[jj] = __float_as_int(p.w);
            sx[j] = p.x; sy[j] = p.y; sz[j] = p.z;
        }
        rd[jj] = 1e10f;
    }
    __syncthreads();

    {
        int bi = INT_MAX, bp = 0;
#pragma unroll
        for (int jj = 0; jj < FPW; jj++) {
            int j = tid + jj * 512;
            if (j < P && rgid[jj] < bi) { bi = rgid[jj]; bp = j; }
        }
        for (int o = 16; o > 0; o >>= 1) {
            int oi = __shfl_down_sync(~0u, bi, o);
            int op = __shfl_down_sync(~0u, bp, o);
            if (oi < bi) { bi = oi; bp = op; }
        }
        if ((tid & 31) == 0) { rid[tid >> 5] = bi; rpos[tid >> 5] = bp; }
        __syncthreads();
        if (tid < 32) {
            int v  = (tid < 16) ? rid[tid]  : INT_MAX;
            int pp = (tid < 16) ? rpos[tid] : 0;
            for (int o = 8; o > 0; o >>= 1) {
                int oi = __shfl_down_sync(~0u, v, o);
                int op = __shfl_down_sync(~0u, pp, o);
                if (oi < v) { v = oi; pp = op; }
            }
            if (tid == 0) {
                ssel[0] = v;
                lastx = sx[pp]; lasty = sy[pp]; lastz = sz[pp];
            }
        }
        __syncthreads();
    }

    for (int it = 1; it < KSEL; it++) {
        float lx = lastx, ly = lasty, lz = lastz;
        float bv = -2.0f; int bi = INT_MAX; int bp = 0;
#pragma unroll
        for (int jj = 0; jj < FPW; jj++) {
            int j = tid + jj * 512;
            if (j < P) {
                float dx = rx[jj] - lx, dy = ry[jj] - ly, dz = rz[jj] - lz;
                float d  = dx * dx + dy * dy + dz * dz;
                float nd = fminf(rd[jj], d);
                rd[jj] = nd;
                if (nd > bv || (nd == bv && rgid[jj] < bi)) { bv = nd; bi = rgid[jj]; bp = j; }
            }
        }
        for (int o = 16; o > 0; o >>= 1) {
            float ov = __shfl_down_sync(~0u, bv, o);
            int   oi = __shfl_down_sync(~0u, bi, o);
            int   op = __shfl_down_sync(~0u, bp, o);
            if (ov > bv || (ov == bv && oi < bi)) { bv = ov; bi = oi; bp = op; }
        }
        if ((tid & 31) == 0) { rv[tid >> 5] = bv; rid[tid >> 5] = bi; rpos[tid >> 5] = bp; }
        __syncthreads();
        if (tid < 32) {
            float v  = (tid < 16) ? rv[tid]   : -3.0f;
            int   id = (tid < 16) ? rid[tid]  : INT_MAX;
            int   pp = (tid < 16) ? rpos[tid] : 0;
            for (int o = 8; o > 0; o >>= 1) {
                float ov = __shfl_down_sync(~0u, v, o);
                int   oi = __shfl_down_sync(~0u, id, o);
                int   op = __shfl_down_sync(~0u, pp, o);
                if (ov > v || (ov == v && oi < id)) { v = ov; id = oi; pp = op; }
            }
            if (tid == 0) {
                ssel[it] = id;
                lastx = sx[pp]; lasty = sy[pp]; lastz = sz[pp];
            }
        }
        __syncthreads();
    }

    for (int e = tid; e < KSEL * FDIM; e += 512) {
        int k = e / FDIM;
        int f = e - k * FDIM;
        g_feat[rowbase + e] = feats[(size_t)ssel[k] * FDIM + f];
    }
}

// ---------------- 3xBF16 split-K GEMM (m16n8k16) ----------------
// Splits to bf16 hi/lo ONCE at smem staging; inner loop is pure LDS + MMA.
__device__ __forceinline__ void split_pack_bf16(float x0, float x1,
                                                unsigned& hi, unsigned& lo) {
    __nv_bfloat162 h = __float22bfloat162_rn(make_float2(x0, x1));
    float r0 = x0 - __bfloat162float(__low2bfloat16(h));
    float r1 = x1 - __bfloat162float(__high2bfloat16(h));
    __nv_bfloat162 l = __float22bfloat162_rn(make_float2(r0, r1));
    hi = *reinterpret_cast<unsigned*>(&h);
    lo = *reinterpret_cast<unsigned*>(&l);
}

#define MMA_BF16(D, A0, A1, A2, A3, B0, B1)                                     \
    asm volatile("mma.sync.aligned.m16n8k16.row.col.f32.bf16.bf16.f32 "         \
                 "{%0,%1,%2,%3},{%4,%5,%6,%7},{%8,%9},{%0,%1,%2,%3};"           \
                 : "+f"(D[0]), "+f"(D[1]), "+f"(D[2]), "+f"(D[3])               \
                 : "r"(A0), "r"(A1), "r"(A2), "r"(A3), "r"(B0), "r"(B1))

__global__ __launch_bounds__(128) void gemm_bf16_kernel(const float* __restrict__ A,
                                                        const float* __restrict__ B,
                                                        int M, int N, int K, int chunk) {
    // [m][kpair] and [n][kpair] packed bf16x2 planes, stride 18 to dodge conflicts
    __shared__ unsigned Ahi[64][18], Alo[64][18];
    __shared__ unsigned Bhi[64][18], Blo[64][18];

    int s  = blockIdx.z;
    int k0 = s * chunk;
    int k1 = k0 + chunk; if (k1 > K) k1 = K;
    int m0 = blockIdx.y * 64, n0 = blockIdx.x * 64;
    int tid = threadIdx.x;
    int lane = tid & 31, w = tid >> 5;
    int wm = w >> 1, wn = w & 1;
    int g = lane >> 2, q = lane & 3;

    float d[2][4][4];
#pragma unroll
    for (int mi = 0; mi < 2; mi++)
#pragma unroll
        for (int ni = 0; ni < 4; ni++)
#pragma unroll
            for (int e = 0; e < 4; e++) d[mi][ni][e] = 0.0f;

    for (int kb = k0; kb < k1; kb += 32) {
        // stage A: 64 rows x 16 kpairs
#pragma unroll
        for (int i = 0; i < 8; i++) {
            int id = tid + i * 128;
            int m = id >> 4, t = id & 15;
            int kg = kb + 2 * t;
            const float* src = &A[(size_t)(m0 + m) * K + kg];
            float x0 = (kg < k1)     ? src[0] : 0.0f;
            float x1 = (kg + 1 < k1) ? src[1] : 0.0f;
            split_pack_bf16(x0, x1, Ahi[m][t], Alo[m][t]);
        }
        // stage B (transposed): 64 cols x 16 kpairs
#pragma unroll
        for (int i = 0; i < 8; i++) {
            int id = tid + i * 128;
            int n = id & 63, t = id >> 6;
            int kg = kb + 2 * t;
            float x0 = (kg < k1)     ? B[(size_t)kg * N + n0 + n]       : 0.0f;
            float x1 = (kg + 1 < k1) ? B[(size_t)(kg + 1) * N + n0 + n] : 0.0f;
            split_pack_bf16(x0, x1, Bhi[n][t], Blo[n][t]);
        }
        __syncthreads();
#pragma unroll
        for (int kk = 0; kk < 2; kk++) {
            int tb = kk * 8;
            unsigned ah[2][4], al[2][4], bh[4][2], bl[4][2];
#pragma unroll
            for (int mi = 0; mi < 2; mi++) {
                int r0 = wm * 32 + mi * 16 + g;
                ah[mi][0] = Ahi[r0][tb + q];         al[mi][0] = Alo[r0][tb + q];
                ah[mi][1] = Ahi[r0 + 8][tb + q];     al[mi][1] = Alo[r0 + 8][tb + q];
                ah[mi][2] = Ahi[r0][tb + q + 4];     al[mi][2] = Alo[r0][tb + q + 4];
                ah[mi][3] = Ahi[r0 + 8][tb + q + 4]; al[mi][3] = Alo[r0 + 8][tb + q + 4];
            }
#pragma unroll
            for (int ni = 0; ni < 4; ni++) {
                int col = wn * 32 + ni * 8 + g;
                bh[ni][0] = Bhi[col][tb + q];        bl[ni][0] = Blo[col][tb + q];
                bh[ni][1] = Bhi[col][tb + q + 4];    bl[ni][1] = Blo[col][tb + q + 4];
            }
#pragma unroll
            for (int mi = 0; mi < 2; mi++)
#pragma unroll
                for (int ni = 0; ni < 4; ni++) {
                    MMA_BF16(d[mi][ni], ah[mi][0], ah[mi][1], ah[mi][2], ah[mi][3],
                             bh[ni][0], bh[ni][1]);
                    MMA_BF16(d[mi][ni], ah[mi][0], ah[mi][1], ah[mi][2], ah[mi][3],
                             bl[ni][0], bl[ni][1]);
                    MMA_BF16(d[mi][ni], al[mi][0], al[mi][1], al[mi][2], al[mi][3],
                             bh[ni][0], bh[ni][1]);
                }
        }
        __syncthreads();
    }

    float* P = g_part + (size_t)s * M * N;
#pragma unroll
    for (int mi = 0; mi < 2; mi++) {
#pragma unroll
        for (int ni = 0; ni < 4; ni++) {
            int m_ = m0 + wm * 32 + mi * 16 + g;
            int n_ = n0 + wn * 32 + ni * 8 + q * 2;
            *(float2*)&P[(size_t)m_ * N + n_]       = make_float2(d[mi][ni][0], d[mi][ni][1]);
            *(float2*)&P[(size_t)(m_ + 8) * N + n_] = make_float2(d[mi][ni][2], d[mi][ni][3]);
        }
    }
}

// ---------------- combine split-K + bias + BatchNorm(train) + optional ReLU ----
__global__ __launch_bounds__(256) void bn_combine_kernel(const float* __restrict__ bias,
                                                         const float* __restrict__ gam,
                                                         const float* __restrict__ bet,
                                                         float* __restrict__ out,
                                                         int M, int N, int S, int relu) {
    __shared__ float red[256];
    __shared__ float cmean[8], cvar[8];
    int t = threadIdx.x;
    int n0 = blockIdx.x * 8;
    int col = n0 + (t & 7);
    int mrow = t >> 3;

    float bn = bias[col];
    float v[8];
    float psum = 0.0f;
#pragma unroll
    for (int j = 0; j < 8; j++) {
        int m = mrow + 32 * j;
        float acc = bn;
        for (int s = 0; s < S; s++)
            acc += g_part[(size_t)s * M * N + (size_t)m * N + col];
        v[j] = acc;
        psum += acc;
    }
    red[t] = psum;
    __syncthreads();
    for (int st = 128; st >= 8; st >>= 1) {
        if (t < st) red[t] += red[t + st];
        __syncthreads();
    }
    if (t < 8) cmean[t] = red[t] / (float)M;
    __syncthreads();
    float mean = cmean[t & 7];

    float pss = 0.0f;
#pragma unroll
    for (int j = 0; j < 8; j++) {
        float dd = v[j] - mean;
        pss += dd * dd;
    }
    red[t] = pss;
    __syncthreads();
    for (int st = 128; st >= 8; st >>= 1) {
        if (t < st) red[t] += red[t + st];
        __syncthreads();
    }
    if (t < 8) cvar[t] = red[t] / (float)M;
    __syncthreads();
    float inv = rsqrtf(cvar[t & 7] + 1e-5f);
    float gm = gam[col], bt = bet[col];

#pragma unroll
    for (int j = 0; j < 8; j++) {
        int m = mrow + 32 * j;
        float y = gm * (v[j] - mean) * inv + bt;
        if (relu) y = fmaxf(y, 0.0f);
        out[(size_t)m * N + col] = y;
    }
}

// ---------------- host ----------------
static void run_layer(const float* X, const float* W, const float* b,
                      const float* g, const float* be, float* Y,
                      int M, int K, int N, int S, int relu) {
    int chunk = ((K + S - 1) / S + 31) & ~31;
    dim3 grid(N / 64, M / 64, S);
    gemm_bf16_kernel<<<grid, 128>>>(X, W, M, N, K, chunk);
    bn_combine_kernel<<<N / 8, 256>>>(b, g, be, Y, M, N, S, relu);
}

extern "C" void kernel_launch(void* const* d_in, const int* in_sizes, int n_in,
                              void* d_out, int out_size) {
    const int*   roi_idx = (const int*)d_in[1];
    const float* feats   = (const float*)d_in[2];
    const float* coords  = (const float*)d_in[3];
    const float* w1 = (const float*)d_in[4],  *b1 = (const float*)d_in[5];
    const float* g1 = (const float*)d_in[6],  *be1 = (const float*)d_in[7];
    const float* w2 = (const float*)d_in[8],  *b2 = (const float*)d_in[9];
    const float* g2 = (const float*)d_in[10], *be2 = (const float*)d_in[11];
    const float* w3 = (const float*)d_in[12], *b3 = (const float*)d_in[13];
    const float* g3 = (const float*)d_in[14], *be3 = (const float*)d_in[15];
    const float* w4 = (const float*)d_in[16], *b4 = (const float*)d_in[17];
    const float* g4 = (const float*)d_in[18], *be4 = (const float*)d_in[19];
    const float* w5 = (const float*)d_in[20], *b5 = (const float*)d_in[21];
    const float* g5 = (const float*)d_in[22], *be5 = (const float*)d_in[23];

    int R  = out_size / 512;
    int Np = in_sizes[1];
    float* out = (float*)d_out;

    float *feat_p, *hA_p, *hB_p;
    cudaGetSymbolAddress((void**)&feat_p, g_feat);
    cudaGetSymbolAddress((void**)&hA_p,  g_hA);
    cudaGetSymbolAddress((void**)&hB_p,  g_hB);

    const int FPS_SMEM = PCAP * 3 * (int)sizeof(float);  // 48KB
    cudaFuncSetAttribute(fps_kernel, cudaFuncAttributeMaxDynamicSharedMemorySize, FPS_SMEM);

    // grouping
    int chunk = (Np + NB - 1) / NB;
    blockhist_kernel<<<NB, 512>>>(roi_idx, Np, chunk);
    totals_scan_kernel<<<1, 256>>>();
    blockbase_kernel<<<RMAX, 256>>>();
    scatter_kernel<<<NB, 512>>>(roi_idx, coords, Np, chunk);

    // FPS + fused gather
    fps_kernel<<<R, 512, FPS_SMEM>>>(feats);

    // MLP (3xBF16 tensor-core GEMMs, split-K everywhere)
    run_layer(feat_p, w1, b1, g1, be1, hA_p, R, KSEL * FDIM, 256, 8, 1);
    run_layer(hA_p,   w2, b2, g2, be2, hB_p, R, 256,          256, 4, 1);
    run_layer(hB_p,   w3, b3, g3, be3, hA_p, R, 256,          512, 4, 0);
    run_layer(hA_p,   w4, b4, g4, be4, hB_p, R, 512,          256, 4, 1);
    run_layer(hB_p,   w5, b5, g5, be5, out,  R, 256,          512, 4, 1);
}

// round 10
// speedup vs baseline: 1.8676x; 1.1561x over previous
#include <cuda_runtime.h>
#include <cuda_bf16.h>
#include <math.h>
#include <limits.h>

// ---------------- problem constants ----------------
#define KSEL   50
#define FDIM   90
#define PCAP   4096
#define RMAX   256
#define NMAX   600000
#define SMAX   16
#define NB     240
#define K1PAD  4608            // layer-1 K padded to 32
#define K1P2   (K1PAD/2)       // 2304 kpairs
#define K1REAL (KSEL*FDIM)     // 4500

// ---------------- device scratch ----------------
__device__ int      g_counts[RMAX];
__device__ int      g_offsets[RMAX];
__device__ int      g_bc[NB * RMAX];
__device__ int      g_bbase[NB * RMAX];
__device__ float4   g_packed[NMAX];
__device__ float    g_part[SMAX * RMAX * 512];
// packed bf16x2 planes
__device__ unsigned g_fhi[RMAX * K1P2], g_flo[RMAX * K1P2];     // layer-1 input
__device__ unsigned g_ahi[RMAX * 256],  g_alo[RMAX * 256];      // act ping (NP<=256)
__device__ unsigned g_bhi[RMAX * 256],  g_blo[RMAX * 256];      // act pong
__device__ unsigned g_w1h[256 * K1P2],  g_w1l[256 * K1P2];
__device__ unsigned g_w2h[256 * 128],   g_w2l[256 * 128];
__device__ unsigned g_w3h[512 * 128],   g_w3l[512 * 128];
__device__ unsigned g_w4h[256 * 256],   g_w4l[256 * 256];
__device__ unsigned g_w5h[512 * 128],   g_w5l[512 * 128];

__device__ __forceinline__ void split_pack_bf16(float x0, float x1,
                                                unsigned& hi, unsigned& lo) {
    __nv_bfloat162 h = __float22bfloat162_rn(make_float2(x0, x1));
    float r0 = x0 - __bfloat162float(__low2bfloat16(h));
    float r1 = x1 - __bfloat162float(__high2bfloat16(h));
    __nv_bfloat162 l = __float22bfloat162_rn(make_float2(r0, r1));
    hi = *reinterpret_cast<unsigned*>(&h);
    lo = *reinterpret_cast<unsigned*>(&l);
}

// ---------------- grouping ----------------
__global__ void blockhist_kernel(const int* __restrict__ idx, int Np, int chunk) {
    __shared__ int sh[RMAX];
    int b = blockIdx.x;
    int t = threadIdx.x;
    if (t < RMAX) sh[t] = 0;
    __syncthreads();
    int i0 = b * chunk;
    int i1 = i0 + chunk; if (i1 > Np) i1 = Np;
    for (int i = i0 + t; i < i1; i += blockDim.x)
        atomicAdd(&sh[idx[i]], 1);
    __syncthreads();
    if (t < RMAX) g_bc[b * RMAX + t] = sh[t];
}

__global__ void totals_scan_kernel() {
    __shared__ int wsum[8];
    int r = threadIdx.x;
    int c = 0;
    for (int b = 0; b < NB; b++) c += g_bc[b * RMAX + r];
    g_counts[r] = c;
    int v = c;
    for (int o = 1; o < 32; o <<= 1) {
        int x = __shfl_up_sync(~0u, v, o);
        if ((r & 31) >= o) v += x;
    }
    if ((r & 31) == 31) wsum[r >> 5] = v;
    __syncthreads();
    if (r < 8) {
        int s = wsum[r];
        for (int o = 1; o < 8; o <<= 1) {
            int x = __shfl_up_sync(0xff, s, o);
            if (r >= o) s += x;
        }
        wsum[r] = s;
    }
    __syncthreads();
    int pre = (r >= 32) ? wsum[(r >> 5) - 1] : 0;
    g_offsets[r] = pre + v - c;
}

__global__ void blockbase_kernel() {
    __shared__ int wsum[8];
    int r = blockIdx.x;
    int t = threadIdx.x;
    int c = (t < NB) ? g_bc[t * RMAX + r] : 0;
    int v = c;
    for (int o = 1; o < 32; o <<= 1) {
        int x = __shfl_up_sync(~0u, v, o);
        if ((t & 31) >= o) v += x;
    }
    if ((t & 31) == 31) wsum[t >> 5] = v;
    __syncthreads();
    if (t < 8) {
        int s = wsum[t];
        for (int o = 1; o < 8; o <<= 1) {
            int x = __shfl_up_sync(0xff, s, o);
            if (t >= o) s += x;
        }
        wsum[t] = s;
    }
    __syncthreads();
    int pre = (t >= 32) ? wsum[(t >> 5) - 1] : 0;
    if (t < NB) g_bbase[t * RMAX + r] = g_offsets[r] + pre + v - c;
}

__global__ void scatter_kernel(const int* __restrict__ idx,
                               const float* __restrict__ coords,
                               int Np, int chunk) {
    __shared__ int sc[RMAX];
    int b = blockIdx.x;
    int t = threadIdx.x;
    if (t < RMAX) sc[t] = g_bbase[b * RMAX + t];
    __syncthreads();
    int i0 = b * chunk;
    int i1 = i0 + chunk; if (i1 > Np) i1 = Np;
    for (int i = i0 + t; i < i1; i += blockDim.x) {
        int r = idx[i];
        int slot = atomicAdd(&sc[r], 1);
        float4 p;
        p.x = coords[3 * i + 0];
        p.y = coords[3 * i + 1];
        p.z = coords[3 * i + 2];
        p.w = __int_as_float(i);
        g_packed[slot] = p;
    }
}

// ---------------- weight transpose + bf16 split (packed planes, [n][kpair]) ----
__global__ __launch_bounds__(256) void wsplit_kernel(const float* __restrict__ w1,
                                                     const float* __restrict__ w2,
                                                     const float* __restrict__ w3,
                                                     const float* __restrict__ w4,
                                                     const float* __restrict__ w5) {
    __shared__ float tile[64][65];
    int b = blockIdx.x;
    const float* w; unsigned *whi, *wlo;
    int N, Kreal, KP, nt, local;
    if (b < 288)      { w = w1; whi = g_w1h; wlo = g_w1l; N = 256; Kreal = K1REAL; KP = K1P2; nt = 4; local = b; }
    else if (b < 304) { w = w2; whi = g_w2h; wlo = g_w2l; N = 256; Kreal = 256; KP = 128; nt = 4; local = b - 288; }
    else if (b < 336) { w = w3; whi = g_w3h; wlo = g_w3l; N = 512; Kreal = 256; KP = 128; nt = 8; local = b - 304; }
    else if (b < 368) { w = w4; whi = g_w4h; wlo = g_w4l; N = 256; Kreal = 512; KP = 256; nt = 4; local = b - 336; }
    else              { w = w5; whi = g_w5h; wlo = g_w5l; N = 512; Kreal = 256; KP = 128; nt = 8; local = b - 368; }
    int tn = local % nt, tk = local / nt;
    int n0 = tn * 64, kb = tk * 64;
    int t = threadIdx.x;
    for (int id = t; id < 4096; id += 256) {
        int kk = id >> 6, nn = id & 63;
        int kg = kb + kk;
        tile[kk][nn] = (kg < Kreal) ? w[(size_t)kg * N + n0 + nn] : 0.0f;
    }
    __syncthreads();
    for (int id = t; id < 2048; id += 256) {
        int n = id >> 5, kp = id & 31;
        unsigned h, l;
        split_pack_bf16(tile[2 * kp][n], tile[2 * kp + 1][n], h, l);
        size_t o = (size_t)(n0 + n) * KP + (kb >> 1) + kp;
        whi[o] = h; wlo[o] = l;
    }
}

// ---------------- FPS (+fused gather to packed planes) ----------------
#define FPW 8
__global__ __launch_bounds__(512, 2) void fps_kernel(const float* __restrict__ feats) {
    extern __shared__ float sm[];
    float* sx = sm;
    float* sy = sx + PCAP;
    float* sz = sy + PCAP;

    __shared__ float rv[16];
    __shared__ int   rid[16], rpos[16];
    __shared__ float lastx, lasty, lastz;
    __shared__ int   ssel[KSEL];

    int r = blockIdx.x;
    int P = g_counts[r];
    if (P > PCAP) P = PCAP;
    int tid = threadIdx.x;
    const size_t rowbase = (size_t)r * K1P2;

    if (P == 0) {
        for (int e = tid; e < K1P2; e += 512) {
            g_fhi[rowbase + e] = 0u;
            g_flo[rowbase + e] = 0u;
        }
        return;
    }
    int off = g_offsets[r];

    float rx[FPW], ry[FPW], rz[FPW], rd[FPW];
    int   rgid[FPW];

#pragma unroll
    for (int jj = 0; jj < FPW; jj++) {
        int j = tid + jj * 512;
        if (j < P) {
            float4 p = g_packed[off + j];
            rx[jj] = p.x; ry[jj] = p.y; rz[jj] = p.z;
            rgid[jj] = __float_as_int(p.w);
            sx[j] = p.x; sy[j] = p.y; sz[j] = p.z;
        }
        rd[jj] = 1e10f;
    }
    __syncthreads();

    {
        int bi = INT_MAX, bp = 0;
#pragma unroll
        for (int jj = 0; jj < FPW; jj++) {
            int j = tid + jj * 512;
            if (j < P && rgid[jj] < bi) { bi = rgid[jj]; bp = j; }
        }
        for (int o = 16; o > 0; o >>= 1) {
            int oi = __shfl_down_sync(~0u, bi, o);
            int op = __shfl_down_sync(~0u, bp, o);
            if (oi < bi) { bi = oi; bp = op; }
        }
        if ((tid & 31) == 0) { rid[tid >> 5] = bi; rpos[tid >> 5] = bp; }
        __syncthreads();
        if (tid < 32) {
            int v  = (tid < 16) ? rid[tid]  : INT_MAX;
            int pp = (tid < 16) ? rpos[tid] : 0;
            for (int o = 8; o > 0; o >>= 1) {
                int oi = __shfl_down_sync(~0u, v, o);
                int op = __shfl_down_sync(~0u, pp, o);
                if (oi < v) { v = oi; pp = op; }
            }
            if (tid == 0) {
                ssel[0] = v;
                lastx = sx[pp]; lasty = sy[pp]; lastz = sz[pp];
            }
        }
        __syncthreads();
    }

    for (int it = 1; it < KSEL; it++) {
        float lx = lastx, ly = lasty, lz = lastz;
        float bv = -2.0f; int bi = INT_MAX; int bp = 0;
#pragma unroll
        for (int jj = 0; jj < FPW; jj++) {
            int j = tid + jj * 512;
            if (j < P) {
                float dx = rx[jj] - lx, dy = ry[jj] - ly, dz = rz[jj] - lz;
                float d  = dx * dx + dy * dy + dz * dz;
                float nd = fminf(rd[jj], d);
                rd[jj] = nd;
                if (nd > bv || (nd == bv && rgid[jj] < bi)) { bv = nd; bi = rgid[jj]; bp = j; }
            }
        }
        for (int o = 16; o > 0; o >>= 1) {
            float ov = __shfl_down_sync(~0u, bv, o);
            int   oi = __shfl_down_sync(~0u, bi, o);
            int   op = __shfl_down_sync(~0u, bp, o);
            if (ov > bv || (ov == bv && oi < bi)) { bv = ov; bi = oi; bp = op; }
        }
        if ((tid & 31) == 0) { rv[tid >> 5] = bv; rid[tid >> 5] = bi; rpos[tid >> 5] = bp; }
        __syncthreads();
        if (tid < 32) {
            float v  = (tid < 16) ? rv[tid]   : -3.0f;
            int   id = (tid < 16) ? rid[tid]  : INT_MAX;
            int   pp = (tid < 16) ? rpos[tid] : 0;
            for (int o = 8; o > 0; o >>= 1) {
                float ov = __shfl_down_sync(~0u, v, o);
                int   oi = __shfl_down_sync(~0u, id, o);
                int   op = __shfl_down_sync(~0u, pp, o);
                if (ov > v || (ov == v && oi < id)) { v = ov; id = oi; pp = op; }
            }
            if (tid == 0) {
                ssel[it] = id;
                lastx = sx[pp]; lasty = sy[pp]; lastz = sz[pp];
            }
        }
        __syncthreads();
    }

    // fused gather -> packed bf16x2 planes, zero-padded to K1P2
    for (int e = tid; e < K1P2; e += 512) {
        unsigned h = 0u, l = 0u;
        if (e < K1REAL / 2) {
            int k2 = 2 * e;
            int p = k2 / FDIM;
            int f = k2 - p * FDIM;          // even, FDIM even -> no straddle
            float2 vv = *(const float2*)&feats[(size_t)ssel[p] * FDIM + f];
            split_pack_bf16(vv.x, vv.y, h, l);
        }
        g_fhi[rowbase + e] = h;
        g_flo[rowbase + e] = l;
    }
}

// ---------------- packed-plane split-K GEMM (3xBF16 m16n8k16, zero conversions) -
#define MMA_BF16(D, A0, A1, A2, A3, B0, B1)                                     \
    asm volatile("mma.sync.aligned.m16n8k16.row.col.f32.bf16.bf16.f32 "         \
                 "{%0,%1,%2,%3},{%4,%5,%6,%7},{%8,%9},{%0,%1,%2,%3};"           \
                 : "+f"(D[0]), "+f"(D[1]), "+f"(D[2]), "+f"(D[3])               \
                 : "r"(A0), "r"(A1), "r"(A2), "r"(A3), "r"(B0), "r"(B1))

__global__ __launch_bounds__(128) void gemm_pk_kernel(const unsigned* __restrict__ Ahi_g,
                                                      const unsigned* __restrict__ Alo_g,
                                                      const unsigned* __restrict__ Bhi_g,
                                                      const unsigned* __restrict__ Blo_g,
                                                      int KP, int M, int N, int chunk2) {
    __shared__ unsigned Ah[64][20], Al[64][20], Bh[64][20], Bl[64][20];
    int s  = blockIdx.z;
    int kp0 = s * chunk2;
    int m0 = blockIdx.y * 64, n0 = blockIdx.x * 64;
    int tid = threadIdx.x;
    int lane = tid & 31, w = tid >> 5;
    int wm = w >> 1, wn = w & 1;
    int g = lane >> 2, q = lane & 3;

    float d[2][4][4];
#pragma unroll
    for (int mi = 0; mi < 2; mi++)
#pragma unroll
        for (int ni = 0; ni < 4; ni++)
#pragma unroll
            for (int e = 0; e < 4; e++) d[mi][ni][e] = 0.0f;

    for (int kb2 = kp0; kb2 < kp0 + chunk2; kb2 += 16) {
        // stage: pure uint4 copies (64 rows x 16 kpairs per plane)
#pragma unroll
        for (int i = 0; i < 2; i++) {
            int id = tid + i * 128;
            int row = id >> 2, c4 = (id & 3) * 4;
            size_t ao = (size_t)(m0 + row) * KP + kb2 + c4;
            size_t bo = (size_t)(n0 + row) * KP + kb2 + c4;
            *(uint4*)&Ah[row][c4] = *(const uint4*)&Ahi_g[ao];
            *(uint4*)&Al[row][c4] = *(const uint4*)&Alo_g[ao];
            *(uint4*)&Bh[row][c4] = *(const uint4*)&Bhi_g[bo];
            *(uint4*)&Bl[row][c4] = *(const uint4*)&Blo_g[bo];
        }
        __syncthreads();
#pragma unroll
        for (int kk = 0; kk < 2; kk++) {
            int tb = kk * 8;
            unsigned ah[2][4], al[2][4], bh[4][2], bl[4][2];
#pragma unroll
            for (int mi = 0; mi < 2; mi++) {
                int r0 = wm * 32 + mi * 16 + g;
                ah[mi][0] = Ah[r0][tb + q];         al[mi][0] = Al[r0][tb + q];
                ah[mi][1] = Ah[r0 + 8][tb + q];     al[mi][1] = Al[r0 + 8][tb + q];
                ah[mi][2] = Ah[r0][tb + q + 4];     al[mi][2] = Al[r0][tb + q + 4];
                ah[mi][3] = Ah[r0 + 8][tb + q + 4]; al[mi][3] = Al[r0 + 8][tb + q + 4];
            }
#pragma unroll
            for (int ni = 0; ni < 4; ni++) {
                int col = wn * 32 + ni * 8 + g;
                bh[ni][0] = Bh[col][tb + q];        bl[ni][0] = Bl[col][tb + q];
                bh[ni][1] = Bh[col][tb + q + 4];    bl[ni][1] = Bl[col][tb + q + 4];
            }
#pragma unroll
            for (int mi = 0; mi < 2; mi++)
#pragma unroll
                for (int ni = 0; ni < 4; ni++) {
                    MMA_BF16(d[mi][ni], ah[mi][0], ah[mi][1], ah[mi][2], ah[mi][3],
                             bh[ni][0], bh[ni][1]);
                    MMA_BF16(d[mi][ni], ah[mi][0], ah[mi][1], ah[mi][2], ah[mi][3],
                             bl[ni][0], bl[ni][1]);
                    MMA_BF16(d[mi][ni], al[mi][0], al[mi][1], al[mi][2], al[mi][3],
                             bh[ni][0], bh[ni][1]);
                }
        }
        __syncthreads();
    }

    float* P = g_part + (size_t)s * M * N;
#pragma unroll
    for (int mi = 0; mi < 2; mi++) {
#pragma unroll
        for (int ni = 0; ni < 4; ni++) {
            int m_ = m0 + wm * 32 + mi * 16 + g;
            int n_ = n0 + wn * 32 + ni * 8 + q * 2;
            *(float2*)&P[(size_t)m_ * N + n_]       = make_float2(d[mi][ni][0], d[mi][ni][1]);
            *(float2*)&P[(size_t)(m_ + 8) * N + n_] = make_float2(d[mi][ni][2], d[mi][ni][3]);
        }
    }
}

// ---------------- combine + bias + BN + ReLU + packed-plane epilogue ----------
// block = 8 columns x 256 rows; thread owns a column-PAIR so packed writes are whole uints
__global__ __launch_bounds__(256) void bnc_kernel(const float* __restrict__ bias,
                                                  const float* __restrict__ gam,
                                                  const float* __restrict__ bet,
                                                  float* __restrict__ outRaw,
                                                  unsigned* __restrict__ outHi,
                                                  unsigned* __restrict__ outLo,
                                                  int M, int N, int S, int relu) {
    __shared__ float2 red[256];
    __shared__ float cm0[4], cm1[4], cv0[4], cv1[4];
    int t = threadIdx.x;
    int n0 = blockIdx.x * 8;
    int cp = t & 3, mr = t >> 2;
    int c0 = n0 + 2 * cp, c1 = c0 + 1;
    int NP = N >> 1;

    float b0 = bias[c0], b1 = bias[c1];
    float v0[4], v1[4];
    float s0 = 0.0f, s1 = 0.0f;
#pragma unroll
    for (int j = 0; j < 4; j++) {
        int m = mr + 64 * j;
        float a0 = b0, a1 = b1;
        for (int s = 0; s < S; s++) {
            size_t base = (size_t)s * M * N + (size_t)m * N;
            a0 += g_part[base + c0];
            a1 += g_part[base + c1];
        }
        v0[j] = a0; v1[j] = a1;
        s0 += a0; s1 += a1;
    }
    red[t] = make_float2(s0, s1);
    __syncthreads();
    for (int st = 128; st >= 4; st >>= 1) {
        if (t < st) { red[t].x += red[t + st].x; red[t].y += red[t + st].y; }
        __syncthreads();
    }
    if (t < 4) { cm0[t] = red[t].x * (1.0f / 256.0f); cm1[t] = red[t].y * (1.0f / 256.0f); }
    __syncthreads();
    float mean0 = cm0[cp], mean1 = cm1[cp];

    float q0 = 0.0f, q1 = 0.0f;
#pragma unroll
    for (int j = 0; j < 4; j++) {
        float d0 = v0[j] - mean0, d1 = v1[j] - mean1;
        q0 += d0 * d0; q1 += d1 * d1;
    }
    red[t] = make_float2(q0, q1);
    __syncthreads();
    for (int st = 128; st >= 4; st >>= 1) {
        if (t < st) { red[t].x += red[t + st].x; red[t].y += red[t + st].y; }
        __syncthreads();
    }
    if (t < 4) { cv0[t] = red[t].x * (1.0f / 256.0f); cv1[t] = red[t].y * (1.0f / 256.0f); }
    __syncthreads();
    float inv0 = rsqrtf(cv0[cp] + 1e-5f);
    float inv1 = rsqrtf(cv1[cp] + 1e-5f);
    float g0 = gam[c0], g1 = gam[c1], be0 = bet[c0], be1 = bet[c1];

#pragma unroll
    for (int j = 0; j < 4; j++) {
        int m = mr + 64 * j;
        float y0 = g0 * (v0[j] - mean0) * inv0 + be0;
        float y1 = g1 * (v1[j] - mean1) * inv1 + be1;
        if (relu) { y0 = fmaxf(y0, 0.0f); y1 = fmaxf(y1, 0.0f); }
        if (outRaw) {
            outRaw[(size_t)m * N + c0] = y0;
            outRaw[(size_t)m * N + c1] = y1;
        }
        if (outHi) {
            unsigned h, l;
            split_pack_bf16(y0, y1, h, l);
            size_t o = (size_t)m * NP + (n0 >> 1) + cp;
            outHi[o] = h; outLo[o] = l;
        }
    }
}

// ---------------- host ----------------
extern "C" void kernel_launch(void* const* d_in, const int* in_sizes, int n_in,
                              void* d_out, int out_size) {
    const int*   roi_idx = (const int*)d_in[1];
    const float* feats   = (const float*)d_in[2];
    const float* coords  = (const float*)d_in[3];
    const float* w1 = (const float*)d_in[4],  *b1 = (const float*)d_in[5];
    const float* g1 = (const float*)d_in[6],  *be1 = (const float*)d_in[7];
    const float* w2 = (const float*)d_in[8],  *b2 = (const float*)d_in[9];
    const float* g2 = (const float*)d_in[10], *be2 = (const float*)d_in[11];
    const float* w3 = (const float*)d_in[12], *b3 = (const float*)d_in[13];
    const float* g3 = (const float*)d_in[14], *be3 = (const float*)d_in[15];
    const float* w4 = (const float*)d_in[16], *b4 = (const float*)d_in[17];
    const float* g4 = (const float*)d_in[18], *be4 = (const float*)d_in[19];
    const float* w5 = (const float*)d_in[20], *b5 = (const float*)d_in[21];
    const float* g5 = (const float*)d_in[22], *be5 = (const float*)d_in[23];

    int R  = out_size / 512;
    int Np = in_sizes[1];
    float* out = (float*)d_out;

    unsigned *fhi, *flo, *ahi, *alo, *bhi, *blo;
    unsigned *w1h, *w1l, *w2h, *w2l, *w3h, *w3l, *w4h, *w4l, *w5h, *w5l;
    cudaGetSymbolAddress((void**)&fhi, g_fhi); cudaGetSymbolAddress((void**)&flo, g_flo);
    cudaGetSymbolAddress((void**)&ahi, g_ahi); cudaGetSymbolAddress((void**)&alo, g_alo);
    cudaGetSymbolAddress((void**)&bhi, g_bhi); cudaGetSymbolAddress((void**)&blo, g_blo);
    cudaGetSymbolAddress((void**)&w1h, g_w1h); cudaGetSymbolAddress((void**)&w1l, g_w1l);
    cudaGetSymbolAddress((void**)&w2h, g_w2h); cudaGetSymbolAddress((void**)&w2l, g_w2l);
    cudaGetSymbolAddress((void**)&w3h, g_w3h); cudaGetSymbolAddress((void**)&w3l, g_w3l);
    cudaGetSymbolAddress((void**)&w4h, g_w4h); cudaGetSymbolAddress((void**)&w4l, g_w4l);
    cudaGetSymbolAddress((void**)&w5h, g_w5h); cudaGetSymbolAddress((void**)&w5l, g_w5l);

    const int FPS_SMEM = PCAP * 3 * (int)sizeof(float);  // 48KB
    cudaFuncSetAttribute(fps_kernel, cudaFuncAttributeMaxDynamicSharedMemorySize, FPS_SMEM);

    // weight transpose/split (packed planes; byte-neutral vs fp32)
    wsplit_kernel<<<400, 256>>>(w1, w2, w3, w4, w5);

    // grouping
    int chunk = (Np + NB - 1) / NB;
    blockhist_kernel<<<NB, 512>>>(roi_idx, Np, chunk);
    totals_scan_kernel<<<1, 256>>>();
    blockbase_kernel<<<RMAX, 256>>>();
    scatter_kernel<<<NB, 512>>>(roi_idx, coords, Np, chunk);

    // FPS + fused gather-to-planes
    fps_kernel<<<R, 512, FPS_SMEM>>>(feats);

    // MLP: 5 x (packed GEMM + BN-combine)
    // L1: K=4608pad, S=9
    gemm_pk_kernel<<<dim3(4, 4, 9), 128>>>(fhi, flo, w1h, w1l, K1P2, R, 256, 256);
    bnc_kernel<<<32, 256>>>(b1, g1, be1, nullptr, ahi, alo, R, 256, 9, 1);
    // L2: K=256, S=4
    gemm_pk_kernel<<<dim3(4, 4, 4), 128>>>(ahi, alo, w2h, w2l, 128, R, 256, 32);
    bnc_kernel<<<32, 256>>>(b2, g2, be2, nullptr, bhi, blo, R, 256, 4, 1);
    // L3: K=256, N=512, S=4 (no relu)
    gemm_pk_kernel<<<dim3(8, 4, 4), 128>>>(bhi, blo, w3h, w3l, 128, R, 512, 32);
    bnc_kernel<<<64, 256>>>(b3, g3, be3, nullptr, ahi, alo, R, 512, 4, 0);
    // L4: K=512, N=256, S=4
    gemm_pk_kernel<<<dim3(4, 4, 4), 128>>>(ahi, alo, w4h, w4l, 256, R, 256, 64);
    bnc_kernel<<<32, 256>>>(b4, g4, be4, nullptr, bhi, blo, R, 256, 4, 1);
    // L5: K=256, N=512, S=4 -> raw fp32 output
    gemm_pk_kernel<<<dim3(8, 4, 4), 128>>>(bhi, blo, w5h, w5l, 128, R, 512, 32);
    bnc_kernel<<<64, 256>>>(b5, g5, be5, out, nullptr, nullptr, R, 512, 4, 1);
}